// round 16
// baseline (speedup 1.0000x reference)
#include <cuda_runtime.h>
#include <cuda_fp16.h>
#include <math.h>

typedef unsigned int u32;

#define F_DIM 512
#define B_DIM 512
#define L_DIM 256
#define C_DIM 128

#define GRID_BLOCKS 128
#define THREADS 256
#define FT    16      // features per CTA
#define NGATE 64      // gate cols per CTA (MMA N)
#define BT    128     // batch rows per CTA (MMA M)
#define KC    128     // k-chunk
#define NCH   4       // chunks per step

#define BST 520       // B row stride fp16 (conflict-free ldmatrix)
#define AST 136       // A row stride fp16 (conflict-free ldmatrix)

// SMEM byte offsets
#define B_PLANE_BYTES (NGATE * BST * 2)          // 66560
#define BHI_OFF 0
#define A_PLANE_BYTES (BT * AST * 2)             // 34816
#define A_OFF   B_PLANE_BYTES
#define ABUF3(i) (A_OFF + (i) * A_PLANE_BYTES)   // 3 buffers
#define SCR_OFF  (A_OFF + 3 * A_PLANE_BYTES)     // 32KB scratch
#define SX_OFF   (SCR_OFF + 32768)
#define SWX_OFF  (SX_OFF + 512)
#define SB_OFF   (SWX_OFF + 256)
#define SMEM_TOTAL (SB_OFF + 2048 + 64)          // ~202 KB

// Persistent device state: h as single fp16 plane [batch][feat]
__device__ __half g_h[2][B_DIM * F_DIM];
#define GRP_STRIDE 32
__device__ unsigned g_cnt[4 * GRP_STRIDE];
__device__ unsigned g_sense[4 * GRP_STRIDE];
#define CKS 32
__device__ unsigned g_ck[4 * NCH * CKS];

__device__ __forceinline__ u32 smem_u32(const void* p) {
    u32 a; asm("{ .reg .u64 t; cvta.to.shared.u64 t, %1; cvt.u32.u64 %0, t; }" : "=r"(a) : "l"(p));
    return a;
}
__device__ __forceinline__ void ldsm_x4(u32* r, u32 addr) {
    asm volatile("ldmatrix.sync.aligned.m8n8.x4.shared.b16 {%0,%1,%2,%3}, [%4];"
                 : "=r"(r[0]), "=r"(r[1]), "=r"(r[2]), "=r"(r[3]) : "r"(addr));
}
__device__ __forceinline__ void mma16816h(float* c, const u32* a, u32 b0, u32 b1) {
    asm volatile("mma.sync.aligned.m16n8k16.row.col.f32.f16.f16.f32 "
                 "{%0,%1,%2,%3}, {%4,%5,%6,%7}, {%8,%9}, {%0,%1,%2,%3};"
                 : "+f"(c[0]), "+f"(c[1]), "+f"(c[2]), "+f"(c[3])
                 : "r"(a[0]), "r"(a[1]), "r"(a[2]), "r"(a[3]), "r"(b0), "r"(b1));
}
__device__ __forceinline__ u32 ld_acq(const unsigned* p) {
    u32 v; asm volatile("ld.acquire.gpu.global.u32 %0, [%1];" : "=r"(v) : "l"(p) : "memory");
    return v;
}
__device__ __forceinline__ void cpasync16(u32 dst, const void* src) {
    asm volatile("cp.async.cg.shared.global [%0], [%1], 16;" :: "r"(dst), "l"(src) : "memory");
}
__device__ __forceinline__ void cp_commit() {
    asm volatile("cp.async.commit_group;" ::: "memory");
}
__device__ __forceinline__ void cp_wait0() {
    asm volatile("cp.async.wait_group 0;" ::: "memory");
}

__device__ __forceinline__ float sigm(float x) {
    const float e = exp2f(-1.4426950408889634f * x);
    return 1.0f / (1.0f + e);
}
__device__ __forceinline__ float tanh_fast(float x) {
    float r; asm("tanh.approx.f32 %0, %1;" : "=f"(r) : "f"(x)); return r;
}

// Full group barrier (32 CTAs of one btile) - init/teardown only.
__device__ __forceinline__ void gsync_grp(unsigned* s_sense, int grp) {
    __syncthreads();
    if (threadIdx.x == 0) {
        unsigned ns = *s_sense ^ 1u;
        *s_sense = ns;
        unsigned* cnt = &g_cnt[grp * GRP_STRIDE];
        unsigned* sen = &g_sense[grp * GRP_STRIDE];
        unsigned old;
        asm volatile("atom.release.gpu.global.add.u32 %0, [%1], %2;"
                     : "=r"(old) : "l"(cnt), "r"(1u) : "memory");
        if (old == 31u) {
            asm volatile("st.relaxed.gpu.global.u32 [%0], %1;" :: "l"(cnt), "r"(0u) : "memory");
            asm volatile("st.release.gpu.global.u32 [%0], %1;" :: "l"(sen), "r"(ns) : "memory");
        } else {
            unsigned v;
            do {
                asm volatile("ld.acquire.gpu.global.u32 %0, [%1];" : "=r"(v) : "l"(sen) : "memory");
            } while (v != ns);
        }
    }
    __syncthreads();
}

__global__ void __launch_bounds__(THREADS, 1)
lstm_hmma_kernel(const float* __restrict__ x,
                 const float* __restrict__ w_gx, const float* __restrict__ w_gh,
                 const float* __restrict__ w_ix, const float* __restrict__ w_ih,
                 const float* __restrict__ w_fx, const float* __restrict__ w_fh,
                 const float* __restrict__ w_ox, const float* __restrict__ w_oh,
                 const float* __restrict__ w_ph,
                 const float* __restrict__ b_g, const float* __restrict__ b_i,
                 const float* __restrict__ b_f, const float* __restrict__ b_o,
                 const float* __restrict__ b_p,
                 float* __restrict__ out)
{
    extern __shared__ char smc[];
    const u32 sbase = smem_u32(smc);
    float*  sx  = (float*)(smc + SX_OFF);
    float*  swx = (float*)(smc + SWX_OFF);
    float*  sbg = (float*)(smc + SB_OFF);
    float*  sbi = sbg + 128;
    float*  sbf = sbi + 128;
    float*  sbo = sbf + 128;
    float4* scr = (float4*)(smc + SCR_OFF);

    const int tid   = threadIdx.x;
    const int bid   = blockIdx.x;
    const int ftile = bid & 31;
    const int btile = bid >> 5;
    const int F0    = ftile * FT;
    const int b0    = btile * BT;
    const int wid   = tid >> 5;
    const int lid   = tid & 31;
    const int wm    = wid >> 2;           // 0..1: batch rows wm*64..+63
    const int wn    = (wid >> 1) & 1;     // 0..1: gates wn*32..+31 (features 8wn..+7)
    const int kh    = wid & 1;            // 0..1: k-half within each chunk
    const int tg    = lid & 3;
    const int q     = lid >> 2;
    const int pl    = tg & 1;             // row-half owned by this lane
    const int mychunk = ftile >> 3;

    __shared__ unsigned s_sense;
    if (tid == 0) s_sense = g_sense[btile * GRP_STRIDE];

    unsigned* ckbase = &g_ck[(btile * NCH) * CKS];
    unsigned* my_ck  = &g_ck[(btile * NCH + mychunk) * CKS];

    // ---- W resident in SMEM: fp16; B[n][k], n = 4*flocal+gate ----
    {
        const float* Wh[4] = {w_gh, w_ih, w_fh, w_oh};
        #pragma unroll 1
        for (int idx = tid; idx < NGATE * F_DIM; idx += THREADS) {
            const int n = idx >> 9;
            const int k = idx & 511;
            const int fl = n >> 2, gt = n & 3;
            const float v = Wh[gt][(F0 + fl) * F_DIM + k];
            *(__half*)(smc + BHI_OFF + ((u32)n * BST + (u32)k) * 2) = __float2half(v);
        }
        if (tid < 64) {
            const int fl = tid >> 2, gt = tid & 3;
            const float* Wx[4] = {w_gx, w_ix, w_fx, w_ox};
            swx[tid] = Wx[gt][F0 + fl];
        }
        // Reference quirk: gate biases broadcast along trailing (batch) axis.
        if (tid < 128) {
            sbg[tid] = b_g[b0 + tid];
            sbi[tid] = b_i[b0 + tid];
            sbf[tid] = b_f[b0 + tid];
            sbo[tid] = b_o[b0 + tid];
        }
    }

    // ---- Zero h plane 0: 32768 grid threads x uint4 covers 512KB ----
    {
        const int gidx = bid * THREADS + tid;
        ((uint4*)g_h[0])[gidx] = make_uint4(0u, 0u, 0u, 0u);
    }
    gsync_grp(&s_sense, btile);

    // ---- ldmatrix per-thread byte offsets ----
    // A m16k16 tiles: rows wm*64 + mt*16 + (lid&7)+8*((lid>>3)&1), col kh*64+8*(lid>>4)
    const u32 a_off0 = (((u32)(wm * 64 + (lid & 7) + 8 * ((lid >> 3) & 1))) * AST
                       + (u32)(kh * 64) + 8u * (u32)(lid >> 4)) * 2u;
    // B n16k16: rows wn*32 + ntp*16 + (lid&7)+8*(lid>>4), col 8*((lid>>3)&1)
    const u32 b_off0 = (((u32)(wn * 32 + (lid & 7) + 8 * (lid >> 4))) * BST
                       + 8u * (u32)((lid >> 3) & 1)) * 2u;
    const u32 bhi_base = sbase + BHI_OFF + b_off0;

    float cst[8];
    #pragma unroll
    for (int i = 0; i < 8; ++i) cst[i] = 0.0f;

    // ---- stage chunk0 of step 0 ----
    {
        #pragma unroll
        for (int qq = 0; qq < 8; ++qq) {
            const int u = tid + qq * 256;
            const int row = u >> 4, seg = u & 15;
            cpasync16(sbase + ABUF3(0) + ((u32)row * AST + (u32)seg * 8u) * 2u,
                      g_h[0] + (size_t)(b0 + row) * F_DIM + seg * 8);
        }
        cp_commit();
    }
    int mbuf = 0, ibuf = 1;

    for (int t = 0; t < L_DIM; ++t) {
        const __half* __restrict__ srch = g_h[t & 1];
        const int dstp = (t & 1) ^ 1;
        const u32 thr = 8u * (u32)t;

        if (tid < BT) sx[tid] = x[(size_t)(b0 + tid) * L_DIM + t];

        float acc[4][4][4];            // [mt][nt][frag]
        #pragma unroll
        for (int mt = 0; mt < 4; ++mt)
            #pragma unroll
            for (int nt = 0; nt < 4; ++nt)
                #pragma unroll
                for (int j = 0; j < 4; ++j) acc[mt][nt][j] = 0.0f;

        u32 pv = ld_acq(ckbase + 1 * CKS);     // speculative poll chunk1

        for (int c = 0; c < NCH; ++c) {
            cp_wait0();
            __syncthreads();

            if (c < NCH - 1) {
                while (pv < thr) pv = ld_acq(ckbase + (c + 1) * CKS);
                #pragma unroll
                for (int qq = 0; qq < 8; ++qq) {
                    const int u = tid + qq * 256;
                    const int row = u >> 4, seg = u & 15;
                    cpasync16(sbase + ABUF3(ibuf) + ((u32)row * AST + (u32)seg * 8u) * 2u,
                              srch + (size_t)(b0 + row) * F_DIM + (c + 1) * KC + seg * 8);
                }
                cp_commit();
                ibuf = (ibuf == 2) ? 0 : ibuf + 1;
                if (c + 2 < NCH) pv = ld_acq(ckbase + (c + 2) * CKS);
            }

            const u32 a_base = sbase + ABUF3(mbuf) + a_off0;
            // Fragment double buffering: ldsm for ks+1 issued before MMAs of ks
            u32 Af[2][4][4], Bf[2][2][4];
            #pragma unroll
            for (int mt = 0; mt < 4; ++mt)
                ldsm_x4(Af[0][mt], a_base + (u32)(mt * 16) * AST * 2u);
            {
                const u32 koff0 = (u32)(c * KC + kh * 64) * 2;
                ldsm_x4(Bf[0][0], bhi_base + koff0);
                ldsm_x4(Bf[0][1], bhi_base + (u32)(16 * BST * 2) + koff0);
            }
            #pragma unroll
            for (int ks = 0; ks < 4; ++ks) {
                const int cur = ks & 1, nxt = cur ^ 1;
                if (ks < 3) {
                    #pragma unroll
                    for (int mt = 0; mt < 4; ++mt)
                        ldsm_x4(Af[nxt][mt], a_base + (u32)(mt * 16) * AST * 2u
                                             + (u32)(ks + 1) * 32u);
                    const u32 koff = (u32)(c * KC + kh * 64 + (ks + 1) * 16) * 2;
                    ldsm_x4(Bf[nxt][0], bhi_base + koff);
                    ldsm_x4(Bf[nxt][1], bhi_base + (u32)(16 * BST * 2) + koff);
                }
                #pragma unroll
                for (int mt = 0; mt < 4; ++mt) {
                    mma16816h(acc[mt][0], Af[cur][mt], Bf[cur][0][0], Bf[cur][0][1]);
                    mma16816h(acc[mt][1], Af[cur][mt], Bf[cur][0][2], Bf[cur][0][3]);
                    mma16816h(acc[mt][2], Af[cur][mt], Bf[cur][1][0], Bf[cur][1][1]);
                    mma16816h(acc[mt][3], Af[cur][mt], Bf[cur][1][2], Bf[cur][1][3]);
                }
            }
            mbuf = (mbuf == 2) ? 0 : mbuf + 1;
        }

        // ---- kh reduction: keep mt pair (kh*2, kh*2+1), exchange the other ----
        {
            #pragma unroll
            for (int jj = 0; jj < 8; ++jj) {
                const int mt2 = jj >> 2, nt = jj & 3;
                const int ms = (1 - kh) * 2 + mt2;
                scr[jj * 256 + tid] = make_float4(acc[ms][nt][0], acc[ms][nt][1],
                                                  acc[ms][nt][2], acc[ms][nt][3]);
            }
            __syncthreads();
            const int ptid = tid ^ 32;     // partner warp (kh flipped)
            #pragma unroll
            for (int jj = 0; jj < 8; ++jj) {
                const int mt2 = jj >> 2, nt = jj & 3;
                const int mk = kh * 2 + mt2;
                const float4 v = scr[jj * 256 + ptid];
                acc[mk][nt][0] += v.x;
                acc[mk][nt][1] += v.y;
                acc[mk][nt][2] += v.z;
                acc[mk][nt][3] += v.w;
            }
        }

        // ---- Epilogue: rows wm*64 + kh*32 + mt2*16 + q + 8*pl ----
        #pragma unroll
        for (int mt2 = 0; mt2 < 2; ++mt2) {
            const int mk = kh * 2 + mt2;
            const int row = wm * 64 + kh * 32 + mt2 * 16 + q + 8 * pl;
            const float xv = sx[row];
            const float bg_ = sbg[row], bi_ = sbi[row], bf_ = sbf[row], bo_ = sbo[row];
            #pragma unroll
            for (int nt = 0; nt < 4; ++nt) {
                const int floc = 8 * wn + 2 * nt + (tg >> 1);
                const float send0 = pl ? acc[mk][nt][0] : acc[mk][nt][2];
                const float send1 = pl ? acc[mk][nt][1] : acc[mk][nt][3];
                const float mine0 = pl ? acc[mk][nt][2] : acc[mk][nt][0];
                const float mine1 = pl ? acc[mk][nt][3] : acc[mk][nt][1];
                const float recv0 = __shfl_xor_sync(0xffffffffu, send0, 1);
                const float recv1 = __shfl_xor_sync(0xffffffffu, send1, 1);
                const float vg = pl ? recv0 : mine0;
                const float vi = pl ? recv1 : mine1;
                const float vf = pl ? mine0 : recv0;
                const float vo = pl ? mine1 : recv1;
                const float wg_ = swx[4*floc + 0], wi_ = swx[4*floc + 1];
                const float wf_ = swx[4*floc + 2], wo_ = swx[4*floc + 3];
                const float pg = vg + wg_ * xv + bg_;
                const float pi = vi + wi_ * xv + bi_;
                const float pf = vf + wf_ * xv + bf_;
                const float po = vo + wo_ * xv + bo_;
                const float gg = tanh_fast(pg);
                const float si = sigm(pi);
                const float sf = sigm(pf);
                const float so = sigm(po);
                const int ci = mt2 * 4 + nt;
                const float cn = gg * si + cst[ci] * sf;
                cst[ci] = cn;
                const float hv = tanh_fast(cn) * so;
                g_h[dstp][(size_t)(b0 + row) * F_DIM + F0 + floc] = __float2half(hv);
            }
        }

        __syncthreads();
        if (tid == 0) {
            unsigned old;
            asm volatile("atom.release.gpu.global.add.u32 %0, [%1], %2;"
                         : "=r"(old) : "l"(my_ck), "r"(1u) : "memory");
        }

        // ---- stage next step's chunk0 ----
        if (t + 1 < L_DIM) {
            const u32 thrn = 8u * (u32)(t + 1);
            while (ld_acq(ckbase + 0 * CKS) < thrn) {}
            const __half* __restrict__ nsrc = g_h[dstp];
            #pragma unroll
            for (int qq = 0; qq < 8; ++qq) {
                const int u = tid + qq * 256;
                const int rr = u >> 4, seg = u & 15;
                cpasync16(sbase + ABUF3(ibuf) + ((u32)rr * AST + (u32)seg * 8u) * 2u,
                          nsrc + (size_t)(b0 + rr) * F_DIM + seg * 8);
            }
            cp_commit();
            ibuf = (ibuf == 2) ? 0 : ibuf + 1;
        }
    }

    // ---- Teardown: group barrier, reset chunk counters (replay safety) ----
    gsync_grp(&s_sense, btile);
    if (ftile == 0 && tid < NCH) {
        asm volatile("st.relaxed.gpu.global.u32 [%0], %1;"
                     :: "l"(ckbase + tid * CKS), "r"(0u) : "memory");
    }

    // ---- Projection: out[b][c] = sum_f h[b][f] * w_ph[f][c] + b_p[c] ----
    {
        const int c2 = (tid & 63) * 2;
        const int brow = bid * 4 + (tid >> 6);
        const __half* __restrict__ hh = g_h[0] + (size_t)brow * F_DIM;
        float a0 = 0.0f, a1 = 0.0f;
        #pragma unroll 4
        for (int f = 0; f < F_DIM; ++f) {
            const float hf = __half2float(hh[f]);
            a0 += hf * w_ph[f * C_DIM + c2];
            a1 += hf * w_ph[f * C_DIM + c2 + 1];
        }
        out[brow * C_DIM + c2]     = a0 + b_p[c2];
        out[brow * C_DIM + c2 + 1] = a1 + b_p[c2 + 1];
    }
}

extern "C" void kernel_launch(void* const* d_in, const int* in_sizes, int n_in,
                              void* d_out, int out_size)
{
    (void)in_sizes; (void)n_in; (void)out_size;
    const float* x    = (const float*)d_in[0];
    const float* w_gx = (const float*)d_in[1];
    const float* w_gh = (const float*)d_in[2];
    const float* w_ix = (const float*)d_in[3];
    const float* w_ih = (const float*)d_in[4];
    const float* w_fx = (const float*)d_in[5];
    const float* w_fh = (const float*)d_in[6];
    const float* w_ox = (const float*)d_in[7];
    const float* w_oh = (const float*)d_in[8];
    const float* w_ph = (const float*)d_in[9];
    const float* b_g  = (const float*)d_in[10];
    const float* b_i  = (const float*)d_in[11];
    const float* b_f  = (const float*)d_in[12];
    const float* b_o  = (const float*)d_in[13];
    const float* b_p  = (const float*)d_in[14];
    float* out = (float*)d_out;

    cudaFuncSetAttribute(lstm_hmma_kernel,
                         cudaFuncAttributeMaxDynamicSharedMemorySize, SMEM_TOTAL);

    lstm_hmma_kernel<<<GRID_BLOCKS, THREADS, SMEM_TOTAL>>>(
        x, w_gx, w_gh, w_ix, w_ih, w_fx, w_fh, w_ox, w_oh, w_ph,
        b_g, b_i, b_f, b_o, b_p, out);
}

// round 17
// speedup vs baseline: 1.4487x; 1.4487x over previous
#include <cuda_runtime.h>
#include <cuda_fp16.h>
#include <math.h>

typedef unsigned int u32;

#define F_DIM 512
#define B_DIM 512
#define L_DIM 256
#define C_DIM 128

#define GRID_BLOCKS 128
#define THREADS 512
#define FT    16      // features per CTA
#define NGATE 64      // gate cols per CTA (MMA N)
#define BT    128     // batch rows per CTA (MMA M)
#define KC    128     // k-chunk
#define NCH   4       // chunks per step

#define BST 520       // B row stride fp16 (conflict-free ldmatrix)
#define AST 136       // A row stride fp16 (conflict-free ldmatrix)

// SMEM byte offsets
#define B_PLANE_BYTES (NGATE * BST * 2)          // 66560
#define BHI_OFF 0
#define A_PLANE_BYTES (BT * AST * 2)             // 34816
#define A_OFF   B_PLANE_BYTES
#define ABUF3(i) (A_OFF + (i) * A_PLANE_BYTES)   // 3 buffers
#define SCR_OFF  (A_OFF + 3 * A_PLANE_BYTES)     // 32KB scratch
#define SX_OFF   (SCR_OFF + 32768)
#define SWX_OFF  (SX_OFF + 512)
#define SB_OFF   (SWX_OFF + 256)
#define SMEM_TOTAL (SB_OFF + 2048 + 64)          // ~202 KB

// Persistent device state: h as single fp16 plane [batch][feat]
__device__ __half g_h[2][B_DIM * F_DIM];
#define GRP_STRIDE 32
__device__ unsigned g_cnt[4 * GRP_STRIDE];
__device__ unsigned g_sense[4 * GRP_STRIDE];
// Per-chunk monotonic counters; now counted in WARP arrivals:
// 8 producer CTAs x 16 warps = 128 arrivals per step.
#define CKS 32
__device__ unsigned g_ck[4 * NCH * CKS];

__device__ __forceinline__ u32 smem_u32(const void* p) {
    u32 a; asm("{ .reg .u64 t; cvta.to.shared.u64 t, %1; cvt.u32.u64 %0, t; }" : "=r"(a) : "l"(p));
    return a;
}
__device__ __forceinline__ void ldsm_x4(u32* r, u32 addr) {
    asm volatile("ldmatrix.sync.aligned.m8n8.x4.shared.b16 {%0,%1,%2,%3}, [%4];"
                 : "=r"(r[0]), "=r"(r[1]), "=r"(r[2]), "=r"(r[3]) : "r"(addr));
}
__device__ __forceinline__ void mma16816h(float* c, const u32* a, u32 b0, u32 b1) {
    asm volatile("mma.sync.aligned.m16n8k16.row.col.f32.f16.f16.f32 "
                 "{%0,%1,%2,%3}, {%4,%5,%6,%7}, {%8,%9}, {%0,%1,%2,%3};"
                 : "+f"(c[0]), "+f"(c[1]), "+f"(c[2]), "+f"(c[3])
                 : "r"(a[0]), "r"(a[1]), "r"(a[2]), "r"(a[3]), "r"(b0), "r"(b1));
}
__device__ __forceinline__ u32 ld_acq(const unsigned* p) {
    u32 v; asm volatile("ld.acquire.gpu.global.u32 %0, [%1];" : "=r"(v) : "l"(p) : "memory");
    return v;
}
__device__ __forceinline__ void red_release(unsigned* p) {
    asm volatile("red.release.gpu.global.add.u32 [%0], %1;" :: "l"(p), "r"(1u) : "memory");
}
__device__ __forceinline__ void cpasync16(u32 dst, const void* src) {
    asm volatile("cp.async.cg.shared.global [%0], [%1], 16;" :: "r"(dst), "l"(src) : "memory");
}
__device__ __forceinline__ void cp_commit() {
    asm volatile("cp.async.commit_group;" ::: "memory");
}
__device__ __forceinline__ void cp_wait0() {
    asm volatile("cp.async.wait_group 0;" ::: "memory");
}
// Lane-0 polls the counter; warp barrier broadcasts completion (cuts L2 spin
// traffic 32x vs all-lane polling).
__device__ __forceinline__ void warp_wait_ge(const unsigned* p, u32 thr, int lid) {
    if (lid == 0) { while (ld_acq(p) < thr) {} }
    __syncwarp();
}

__device__ __forceinline__ float sigm(float x) {
    const float e = exp2f(-1.4426950408889634f * x);
    return 1.0f / (1.0f + e);
}
__device__ __forceinline__ float tanh_fast(float x) {
    float r; asm("tanh.approx.f32 %0, %1;" : "=f"(r) : "f"(x)); return r;
}

// Full group barrier (32 CTAs of one btile) - init/teardown only.
__device__ __forceinline__ void gsync_grp(unsigned* s_sense, int grp) {
    __syncthreads();
    if (threadIdx.x == 0) {
        unsigned ns = *s_sense ^ 1u;
        *s_sense = ns;
        unsigned* cnt = &g_cnt[grp * GRP_STRIDE];
        unsigned* sen = &g_sense[grp * GRP_STRIDE];
        unsigned old;
        asm volatile("atom.release.gpu.global.add.u32 %0, [%1], %2;"
                     : "=r"(old) : "l"(cnt), "r"(1u) : "memory");
        if (old == 31u) {
            asm volatile("st.relaxed.gpu.global.u32 [%0], %1;" :: "l"(cnt), "r"(0u) : "memory");
            asm volatile("st.release.gpu.global.u32 [%0], %1;" :: "l"(sen), "r"(ns) : "memory");
        } else {
            unsigned v;
            do {
                asm volatile("ld.acquire.gpu.global.u32 %0, [%1];" : "=r"(v) : "l"(sen) : "memory");
            } while (v != ns);
        }
    }
    __syncthreads();
}

__global__ void __launch_bounds__(THREADS, 1)
lstm_hmma_kernel(const float* __restrict__ x,
                 const float* __restrict__ w_gx, const float* __restrict__ w_gh,
                 const float* __restrict__ w_ix, const float* __restrict__ w_ih,
                 const float* __restrict__ w_fx, const float* __restrict__ w_fh,
                 const float* __restrict__ w_ox, const float* __restrict__ w_oh,
                 const float* __restrict__ w_ph,
                 const float* __restrict__ b_g, const float* __restrict__ b_i,
                 const float* __restrict__ b_f, const float* __restrict__ b_o,
                 const float* __restrict__ b_p,
                 float* __restrict__ out)
{
    extern __shared__ char smc[];
    const u32 sbase = smem_u32(smc);
    float*  sx  = (float*)(smc + SX_OFF);
    float*  swx = (float*)(smc + SWX_OFF);
    float*  sbg = (float*)(smc + SB_OFF);
    float*  sbi = sbg + 128;
    float*  sbf = sbi + 128;
    float*  sbo = sbf + 128;
    float4* scr = (float4*)(smc + SCR_OFF);

    const int tid   = threadIdx.x;
    const int bid   = blockIdx.x;
    const int ftile = bid & 31;
    const int btile = bid >> 5;
    const int F0    = ftile * FT;
    const int b0    = btile * BT;
    const int wid   = tid >> 5;
    const int lid   = tid & 31;
    const int wm    = wid >> 2;           // 0..3: batch rows wm*32..+31
    const int wn    = (wid >> 1) & 1;     // 0..1: gates wn*32..+31 (features 8wn..+7)
    const int kh    = wid & 1;            // 0..1: k-half within each chunk
    const int tg    = lid & 3;
    const int q     = lid >> 2;
    const int pl    = tg & 1;             // row-half owned by this lane
    const int mychunk = ftile >> 3;

    __shared__ unsigned s_sense;
    if (tid == 0) s_sense = g_sense[btile * GRP_STRIDE];

    unsigned* ckbase = &g_ck[(btile * NCH) * CKS];
    unsigned* my_ck  = &g_ck[(btile * NCH + mychunk) * CKS];

    // ---- W resident in SMEM: fp16; B[n][k], n = 4*flocal+gate ----
    {
        const float* Wh[4] = {w_gh, w_ih, w_fh, w_oh};
        #pragma unroll 1
        for (int idx = tid; idx < NGATE * F_DIM; idx += THREADS) {
            const int n = idx >> 9;
            const int k = idx & 511;
            const int fl = n >> 2, gt = n & 3;
            const float v = Wh[gt][(F0 + fl) * F_DIM + k];
            *(__half*)(smc + BHI_OFF + ((u32)n * BST + (u32)k) * 2) = __float2half(v);
        }
        if (tid < 64) {
            const int fl = tid >> 2, gt = tid & 3;
            const float* Wx[4] = {w_gx, w_ix, w_fx, w_ox};
            swx[tid] = Wx[gt][F0 + fl];
        }
        // Reference quirk: gate biases broadcast along trailing (batch) axis.
        if (tid < 128) {
            sbg[tid] = b_g[b0 + tid];
            sbi[tid] = b_i[b0 + tid];
            sbf[tid] = b_f[b0 + tid];
            sbo[tid] = b_o[b0 + tid];
        }
    }

    // ---- Zero h plane 0 ----
    {
        const int gidx = bid * THREADS + tid;
        ((uint2*)g_h[0])[gidx] = make_uint2(0u, 0u);
    }
    gsync_grp(&s_sense, btile);

    // ---- ldmatrix per-thread byte offsets ----
    // A m16k16 tile (mt adds 16 rows): rows wm*32+(lid&7)+8*((lid>>3)&1), col kh*64+8*(lid>>4)
    const u32 a_off0 = (((u32)(wm * 32 + (lid & 7) + 8 * ((lid >> 3) & 1))) * AST
                       + (u32)(kh * 64) + 8u * (u32)(lid >> 4)) * 2u;
    // B n16k16: rows wn*32+ntp*16+(lid&7)+8*(lid>>4), col 8*((lid>>3)&1)
    const u32 b_off0 = (((u32)(wn * 32 + (lid & 7) + 8 * (lid >> 4))) * BST
                       + 8u * (u32)((lid >> 3) & 1)) * 2u;
    const u32 bhi_base = sbase + BHI_OFF + b_off0;

    float cst[4];
    #pragma unroll
    for (int i = 0; i < 4; ++i) cst[i] = 0.0f;

    // ---- stage chunk0 of step 0 (plane 0 zeroed & group-synced) ----
    {
        #pragma unroll
        for (int qq = 0; qq < 4; ++qq) {
            const int u = tid + qq * 512;
            const int row = u >> 4, seg = u & 15;
            cpasync16(sbase + ABUF3(0) + ((u32)row * AST + (u32)seg * 8u) * 2u,
                      g_h[0] + (size_t)(b0 + row) * F_DIM + seg * 8);
        }
        cp_commit();
    }
    int mbuf = 0, ibuf = 1;

    for (int t = 0; t < L_DIM; ++t) {
        const __half* __restrict__ srch = g_h[t & 1];
        const int dstp = (t & 1) ^ 1;
        const u32 thr = 128u * (u32)t;    // 8 CTAs x 16 warps per chunk per step

        if (tid < BT) sx[tid] = x[(size_t)(b0 + tid) * L_DIM + t];

        float acc[2][4][4];            // [mt][nt][frag]
        #pragma unroll
        for (int mt = 0; mt < 2; ++mt)
            #pragma unroll
            for (int nt = 0; nt < 4; ++nt)
                #pragma unroll
                for (int j = 0; j < 4; ++j) acc[mt][nt][j] = 0.0f;

        for (int c = 0; c < NCH; ++c) {
            cp_wait0();                // my chunk-c slices arrived
            __syncthreads();           // everyone's waits done + all MMA c-1 done

            if (c < NCH - 1) {
                warp_wait_ge(ckbase + (c + 1) * CKS, thr, lid);
                #pragma unroll
                for (int qq = 0; qq < 4; ++qq) {
                    const int u = tid + qq * 512;
                    const int row = u >> 4, seg = u & 15;
                    cpasync16(sbase + ABUF3(ibuf) + ((u32)row * AST + (u32)seg * 8u) * 2u,
                              srch + (size_t)(b0 + row) * F_DIM + (c + 1) * KC + seg * 8);
                }
                cp_commit();
                ibuf = (ibuf == 2) ? 0 : ibuf + 1;
            }

            const u32 a_base = sbase + ABUF3(mbuf) + a_off0;
            #pragma unroll
            for (int ks = 0; ks < 4; ++ks) {
                u32 A0[4], A1[4], B0[4], B1[4];
                ldsm_x4(A0, a_base + ks * 32);
                ldsm_x4(A1, a_base + ks * 32 + 16 * AST * 2);
                const u32 koff = (u32)(c * KC + kh * 64 + ks * 16) * 2;
                ldsm_x4(B0, bhi_base + koff);
                ldsm_x4(B1, bhi_base + (u32)(16 * BST * 2) + koff);
                mma16816h(acc[0][0], A0, B0[0], B0[1]);
                mma16816h(acc[0][1], A0, B0[2], B0[3]);
                mma16816h(acc[1][0], A1, B0[0], B0[1]);
                mma16816h(acc[1][1], A1, B0[2], B0[3]);
                mma16816h(acc[0][2], A0, B1[0], B1[1]);
                mma16816h(acc[0][3], A0, B1[2], B1[3]);
                mma16816h(acc[1][2], A1, B1[0], B1[1]);
                mma16816h(acc[1][3], A1, B1[2], B1[3]);
            }
            mbuf = (mbuf == 2) ? 0 : mbuf + 1;
        }

        // ---- kh reduction: keep mt=kh, exchange mt=1-kh via scratch ----
        {
            float snd[16];
            #pragma unroll
            for (int i = 0; i < 16; ++i)
                snd[i] = kh ? acc[0][i >> 2][i & 3] : acc[1][i >> 2][i & 3];
            #pragma unroll
            for (int j = 0; j < 4; ++j)
                scr[j * 512 + tid] = make_float4(snd[4*j], snd[4*j+1], snd[4*j+2], snd[4*j+3]);
            __syncthreads();
            const int ptid = tid ^ 32;     // partner warp (kh flipped)
            #pragma unroll
            for (int j = 0; j < 4; ++j) {
                const float4 v = scr[j * 512 + ptid];
                const int nt = j;
                acc[0][nt][0] = (kh ? acc[1][nt][0] : acc[0][nt][0]) + v.x;
                acc[0][nt][1] = (kh ? acc[1][nt][1] : acc[0][nt][1]) + v.y;
                acc[0][nt][2] = (kh ? acc[1][nt][2] : acc[0][nt][2]) + v.z;
                acc[0][nt][3] = (kh ? acc[1][nt][3] : acc[0][nt][3]) + v.w;
            }
        }

        // ---- Epilogue (this warp's mt = kh), rh-split across lane pairs ----
        const int row = wm * 32 + kh * 16 + q + 8 * pl;
        const float xv = sx[row];
        const float bg_ = sbg[row], bi_ = sbi[row], bf_ = sbf[row], bo_ = sbo[row];
        #pragma unroll
        for (int nt = 0; nt < 4; ++nt) {
            const int floc = 8 * wn + 2 * nt + (tg >> 1);
            const float send0 = pl ? acc[0][nt][0] : acc[0][nt][2];
            const float send1 = pl ? acc[0][nt][1] : acc[0][nt][3];
            const float mine0 = pl ? acc[0][nt][2] : acc[0][nt][0];
            const float mine1 = pl ? acc[0][nt][3] : acc[0][nt][1];
            const float recv0 = __shfl_xor_sync(0xffffffffu, send0, 1);
            const float recv1 = __shfl_xor_sync(0xffffffffu, send1, 1);
            const float vg = pl ? recv0 : mine0;
            const float vi = pl ? recv1 : mine1;
            const float vf = pl ? mine0 : recv0;
            const float vo = pl ? mine1 : recv1;
            const float wg_ = swx[4*floc + 0], wi_ = swx[4*floc + 1];
            const float wf_ = swx[4*floc + 2], wo_ = swx[4*floc + 3];
            const float pg = vg + wg_ * xv + bg_;
            const float pi = vi + wi_ * xv + bi_;
            const float pf = vf + wf_ * xv + bf_;
            const float po = vo + wo_ * xv + bo_;
            const float gg = tanh_fast(pg);
            const float si = sigm(pi);
            const float sf = sigm(pf);
            const float so = sigm(po);
            const float cn = gg * si + cst[nt] * sf;
            cst[nt] = cn;
            const float hv = tanh_fast(cn) * so;
            g_h[dstp][(size_t)(b0 + row) * F_DIM + F0 + floc] = __float2half(hv);
        }

        // Per-WARP producer arrive: warp barrier gives HB over all lanes' h
        // stores; lane-0 release publishes them. Consumers see chunks as soon
        // as each producer warp finishes (no CTA-straggler wait).
        __syncwarp();
        if (lid == 0) red_release(my_ck);
        __syncthreads();               // protects sx for next step's overwrite

        // ---- stage next step's chunk0 (overlaps other CTAs' tails) ----
        if (t + 1 < L_DIM) {
            const u32 thrn = 128u * (u32)(t + 1);
            warp_wait_ge(ckbase + 0 * CKS, thrn, lid);
            const __half* __restrict__ nsrc = g_h[dstp];
            #pragma unroll
            for (int qq = 0; qq < 4; ++qq) {
                const int u = tid + qq * 512;
                const int rr = u >> 4, seg = u & 15;
                cpasync16(sbase + ABUF3(ibuf) + ((u32)rr * AST + (u32)seg * 8u) * 2u,
                          nsrc + (size_t)(b0 + rr) * F_DIM + seg * 8);
            }
            cp_commit();
            ibuf = (ibuf == 2) ? 0 : ibuf + 1;
        }
    }

    // ---- Teardown: group barrier, reset chunk counters (replay safety) ----
    gsync_grp(&s_sense, btile);
    if (ftile == 0 && tid < NCH) {
        asm volatile("st.relaxed.gpu.global.u32 [%0], %1;"
                     :: "l"(ckbase + tid * CKS), "r"(0u) : "memory");
    }

    // ---- Projection: out[b][c] = sum_f h[b][f] * w_ph[f][c] + b_p[c] ----
    {
        const int cc = tid & 127;
        const int brow = bid * 4 + (tid >> 7);
        const __half* __restrict__ hh = g_h[0] + (size_t)brow * F_DIM;
        float a0 = 0.0f;
        #pragma unroll 4
        for (int f = 0; f < F_DIM; ++f) {
            a0 += __half2float(hh[f]) * w_ph[f * C_DIM + cc];
        }
        out[brow * C_DIM + cc] = a0 + b_p[cc];
    }
}

extern "C" void kernel_launch(void* const* d_in, const int* in_sizes, int n_in,
                              void* d_out, int out_size)
{
    (void)in_sizes; (void)n_in; (void)out_size;
    const float* x    = (const float*)d_in[0];
    const float* w_gx = (const float*)d_in[1];
    const float* w_gh = (const float*)d_in[2];
    const float* w_ix = (const float*)d_in[3];
    const float* w_ih = (const float*)d_in[4];
    const float* w_fx = (const float*)d_in[5];
    const float* w_fh = (const float*)d_in[6];
    const float* w_ox = (const float*)d_in[7];
    const float* w_oh = (const float*)d_in[8];
    const float* w_ph = (const float*)d_in[9];
    const float* b_g  = (const float*)d_in[10];
    const float* b_i  = (const float*)d_in[11];
    const float* b_f  = (const float*)d_in[12];
    const float* b_o  = (const float*)d_in[13];
    const float* b_p  = (const float*)d_in[14];
    float* out = (float*)d_out;

    cudaFuncSetAttribute(lstm_hmma_kernel,
                         cudaFuncAttributeMaxDynamicSharedMemorySize, SMEM_TOTAL);

    lstm_hmma_kernel<<<GRID_BLOCKS, THREADS, SMEM_TOTAL>>>(
        x, w_gx, w_gh, w_ix, w_ih, w_fx, w_fh, w_ox, w_oh, w_ph,
        b_g, b_i, b_f, b_o, b_p, out);
}